// round 6
// baseline (speedup 1.0000x reference)
#include <cuda_runtime.h>
#include <math.h>

// Problem constants (match reference)
#define BB   4
#define VV   20000
#define PP   400000
#define NNN  50000
#define MPP  32
#define MMG  64            // grid M
#define THRESH_F 1.0f
#define W_CONG_F 0.5f

#define NET_BLOCKS 74      // 74*4 = 296 = 148 SMs * 2 -> one balanced wave

// log2(e) folded constants
#define GL2  14.426950408889634f   // GAMMA * log2(e),  GAMMA = 10
#define KL2  2.8853900817779268f   // K_SOFT * log2(e), K_SOFT = 2
#define LN2_OVER_GAMMA 0.069314718055994531f  // ln(2)/GAMMA
#define FPSCALE 33554432.0f        // 2^25 fixed-point scale for REDUX.SUM

// ---------------- scratch (device globals; no allocation allowed) ----------
__device__ float4 g_macro[BB * VV];            // {x, y, c, s} packed
__device__ float2 g_pin_pos[BB * PP];          // 12.8 MB
__device__ float  g_rudy[BB][MMG * MMG];       // 64 KB
__device__ float  g_hpwl[BB];
__device__ float  g_pen[BB];
__device__ unsigned g_cnt[BB];

// monotonic float <-> uint encoding for REDUX min/max on floats
__device__ __forceinline__ unsigned fenc(float x) {
    unsigned b = __float_as_uint(x);
    return b ^ (((unsigned)((int)b >> 31)) | 0x80000000u);
}
__device__ __forceinline__ float fdec(unsigned u) {
    unsigned b = u ^ ((~(unsigned)((int)u >> 31)) | 0x80000000u);
    return __uint_as_float(b);
}

__device__ __forceinline__ unsigned to_tf32(float x) {
    unsigned r;
    asm("cvt.rna.tf32.f32 %0, %1;" : "=r"(r) : "f"(x));
    return r;
}

__device__ __forceinline__ void mma_tf32(float& c0, float& c1, float& c2, float& c3,
                                         unsigned a0, unsigned a1, unsigned a2, unsigned a3,
                                         unsigned b0, unsigned b1) {
    asm volatile("mma.sync.aligned.m16n8k8.row.col.f32.tf32.tf32.f32 "
                 "{%0,%1,%2,%3}, {%4,%5,%6,%7}, {%8,%9}, {%0,%1,%2,%3};"
                 : "+f"(c0), "+f"(c1), "+f"(c2), "+f"(c3)
                 : "r"(a0), "r"(a1), "r"(a2), "r"(a3), "r"(b0), "r"(b1));
}

// ---------------------------------------------------------------------------
// Phase A0: pack {pos.x, pos.y, cos, sin} per (b, macro); zero accumulators.
__global__ __launch_bounds__(256) void macro_prep_kernel(
    const float* __restrict__ positions,      // (B,V,2)
    const float* __restrict__ rot_onehot)     // (B,V,4)
{
    int idx = blockIdx.x * blockDim.x + threadIdx.x;

    if (blockIdx.x < 64) {
        (&g_rudy[0][0])[idx] = 0.0f;
        if (idx < BB) { g_hpwl[idx] = 0.0f; g_pen[idx] = 0.0f; g_cnt[idx] = 0u; }
    }

    if (idx >= BB * VV) return;
    float2 pos = ((const float2*)positions)[idx];
    float4 oh  = ((const float4*)rot_onehot)[idx];
    g_macro[idx] = make_float4(pos.x, pos.y, oh.x - oh.z, oh.y - oh.w);
}

// ---------------------------------------------------------------------------
// Phase A: pin positions. One thread = one pin x 4 batches (single gather per
// batch, p2m/offsets loaded once, MLP=4).
__global__ __launch_bounds__(256) void pin_pos_kernel(
    const int*   __restrict__ pin_to_macro,   // (P,)
    const float* __restrict__ pin_offsets)    // (P,2)
{
    int p = blockIdx.x * blockDim.x + threadIdx.x;
    if (p >= PP) return;
    int m = pin_to_macro[p];
    float2 off = ((const float2*)pin_offsets)[p];

    float4 mac[BB];
#pragma unroll
    for (int b = 0; b < BB; b++) mac[b] = g_macro[b * VV + m];
#pragma unroll
    for (int b = 0; b < BB; b++) {
        float2 pp;
        pp.x = mac[b].x + mac[b].z * off.x - mac[b].w * off.y;
        pp.y = mac[b].y + mac[b].w * off.x + mac[b].z * off.y;
        g_pin_pos[b * PP + p] = pp;
    }
}

// ---------------------------------------------------------------------------
// Phase B: per-net soft-HPWL + bbox + rank-16 RUDY accumulation via tf32 MMA.
// Double-buffered smem, ONE barrier per 16-net chunk.
__global__ __launch_bounds__(256) void net_kernel(
    const int*   __restrict__ net_to_pin,     // (NN,MP)
    const float* __restrict__ net_weights)    // (NN,)
{
    __shared__ unsigned XsT[2][MMG][17];   // [buf][cell][k] tf32 bits
    __shared__ unsigned YsT[2][MMG][17];

    const int b    = blockIdx.y;
    const int tid  = threadIdx.x;
    const int w    = tid >> 5;
    const int lane = tid & 31;
    const int g    = lane >> 2;      // group id 0..7
    const int tg   = lane & 3;       // thread-in-group 0..3
    const int rm   = (w & 3) * 16;   // warp's m (row) origin
    const int cn   = (w >> 2) * 32;  // warp's n (col) origin

    const int netsPerBlock = (NNN + NET_BLOCKS - 1) / NET_BLOCKS;   // 676
    const int n0 = blockIdx.x * netsPerBlock;
    const int n1 = min(n0 + netsPerBlock, NNN);
    const int nchunks = (n1 - n0 + 15) >> 4;

    // per-lane constant factors of the separable sigmoid exponentials
    float Cf[2], Df[2];
#pragma unroll
    for (int t = 0; t < 2; t++) {
        float gg = (float)(lane + t * 32);
        Cf[t] = exp2f(KL2 * (31.5f - gg));
        Df[t] = exp2f(KL2 * (gg - 32.0f));
    }

    float acc[4][4];   // [n-tile][c0..c3]
#pragma unroll
    for (int nt = 0; nt < 4; nt++)
#pragma unroll
        for (int c = 0; c < 4; c++) acc[nt][c] = 0.0f;

    float hp = 0.0f;   // meaningful on lane 0

    for (int ci = 0; ci < nchunks; ci++) {
        const int base = n0 + ci * 16;
        const int p = ci & 1;

        float Fax[2], Fbx[2], Fay[2], Fby[2], ivbs[2];
        bool act[2];

#pragma unroll
        for (int q = 0; q < 2; q++) {
            const int n = base + w + q * 8;
            act[q] = (n < n1);
            Fax[q] = Fbx[q] = Fay[q] = Fby[q] = ivbs[q] = 0.0f;
            if (act[q]) {
                int j = net_to_pin[n * MPP + lane];
                bool valid = (j >= 0);
                int sj = j < 0 ? 0 : j;
                float2 pp = g_pin_pos[b * PP + sj];
                float px = pp.x, py = pp.y;

                unsigned ex = fenc(px);
                unsigned ey = fenc(py);
                float vxM = fdec(__reduce_max_sync(0xffffffffu, valid ? ex : 0u));
                float vxm = fdec(__reduce_min_sync(0xffffffffu, valid ? ex : 0xffffffffu));
                float vyM = fdec(__reduce_max_sync(0xffffffffu, valid ? ey : 0u));
                float vym = fdec(__reduce_min_sync(0xffffffffu, valid ? ey : 0xffffffffu));

                // LSE sums via fixed-point REDUX.SUM (terms in [0,1];
                // invalid lanes contribute exactly 0, matching reference)
                float exM = valid ? exp2f( GL2 * (px - vxM)) : 0.0f;
                float exm = valid ? exp2f(-GL2 * (px - vxm)) : 0.0f;
                float eyM = valid ? exp2f( GL2 * (py - vyM)) : 0.0f;
                float eym = valid ? exp2f(-GL2 * (py - vym)) : 0.0f;
                unsigned sxM = __reduce_add_sync(0xffffffffu, (unsigned)__float2uint_rn(exM * FPSCALE));
                unsigned sxm = __reduce_add_sync(0xffffffffu, (unsigned)__float2uint_rn(exm * FPSCALE));
                unsigned syM = __reduce_add_sync(0xffffffffu, (unsigned)__float2uint_rn(eyM * FPSCALE));
                unsigned sym = __reduce_add_sync(0xffffffffu, (unsigned)__float2uint_rn(eym * FPSCALE));

                if (lane == 0) {
                    // log2 of product of the 4 scaled sums; remove 4*25 bias
                    float prod = ((float)sxM * (float)sxm) *
                                 ((float)syM * (float)sym);
                    float wl = (vxM - vxm) + (vyM - vym)
                             + (__log2f(prod) - 100.0f) * LN2_OVER_GAMMA;
                    hp += wl * net_weights[n];
                }

                float bxm = (vxm + 1.0f) * 0.5f * (MMG - 1);
                float bxM = (vxM + 1.0f) * 0.5f * (MMG - 1);
                float bym = (vym + 1.0f) * 0.5f * (MMG - 1);
                float byM = (vym * 0.0f + vyM + 1.0f) * 0.5f * (MMG - 1);
                float bsize = fmaxf((bxM - bxm + 1.0f) * (byM - bym + 1.0f), 1.0f);
                ivbs[q] = __fdividef(1.0f, bsize);

                Fax[q] = exp2f(KL2 * (bxm - 32.0f));
                Fbx[q] = exp2f(KL2 * (31.5f - bxM));
                Fay[q] = exp2f(KL2 * (bym - 32.0f));
                Fby[q] = exp2f(KL2 * (31.5f - byM));
            }
        }

#pragma unroll
        for (int t = 0; t < 2; t++) {
            const int gi = lane + t * 32;
#pragma unroll
            for (int q = 0; q < 2; q++) {
                float xv = 0.0f, yv = 0.0f;
                if (act[q]) {
                    float ex0 = fminf(Fax[q] * Cf[t], 1e18f);
                    float ex1 = fminf(Fbx[q] * Df[t], 1e18f);
                    float ey0 = fminf(Fay[q] * Cf[t], 1e18f);
                    float ey1 = fminf(Fby[q] * Df[t], 1e18f);
                    float Px = (1.0f + ex0) * (1.0f + ex1);
                    float Py = (1.0f + ey0) * (1.0f + ey1);
                    float R  = __fdividef(1.0f, Px * Py);
                    xv = Py * R;
                    yv = ivbs[q] * Px * R;
                }
                XsT[p][gi][w + q * 8] = to_tf32(xv);
                YsT[p][gi][w + q * 8] = to_tf32(yv);
            }
        }
        __syncthreads();

        // rank-16 update: D[i][j] += sum_k Y[k][i] * X[k][j]
#pragma unroll
        for (int ks = 0; ks < 2; ks++) {
            const int k0 = ks * 8;
            unsigned a0 = YsT[p][rm + g    ][k0 + tg    ];
            unsigned a1 = YsT[p][rm + g + 8][k0 + tg    ];
            unsigned a2 = YsT[p][rm + g    ][k0 + tg + 4];
            unsigned a3 = YsT[p][rm + g + 8][k0 + tg + 4];
#pragma unroll
            for (int nt = 0; nt < 4; nt++) {
                unsigned b0 = XsT[p][cn + nt * 8 + g][k0 + tg    ];
                unsigned b1 = XsT[p][cn + nt * 8 + g][k0 + tg + 4];
                mma_tf32(acc[nt][0], acc[nt][1], acc[nt][2], acc[nt][3],
                         a0, a1, a2, a3, b0, b1);
            }
        }
        // no trailing barrier: next iteration writes the other buffer; reuse
        // of this buffer is protected by the next iteration's barrier.
    }

    // writeback
    {
        const int r0 = rm + g;
        const int r1 = rm + g + 8;
#pragma unroll
        for (int nt = 0; nt < 4; nt++) {
            const int col = cn + nt * 8 + 2 * tg;
            atomicAdd(&g_rudy[b][r0 * MMG + col    ], acc[nt][0]);
            atomicAdd(&g_rudy[b][r0 * MMG + col + 1], acc[nt][1]);
            atomicAdd(&g_rudy[b][r1 * MMG + col    ], acc[nt][2]);
            atomicAdd(&g_rudy[b][r1 * MMG + col + 1], acc[nt][3]);
        }
    }

    if (lane == 0) atomicAdd(&g_hpwl[b], hp);
}

// ---------------------------------------------------------------------------
// Phase C: 7x7 Gaussian smooth (zero-padded) + overflow penalty + finalize.
__global__ __launch_bounds__(256) void conv_kernel(float* __restrict__ out)
{
    __shared__ float tile[10][MMG];
    __shared__ float red[8];
    const int b     = blockIdx.y;
    const int slice = blockIdx.x;
    const int tid   = threadIdx.x;
    const int r0    = slice * 4;

    for (int i = tid; i < 10 * MMG; i += 256) {
        int rr = r0 - 3 + (i >> 6);
        int cc = i & 63;
        tile[i >> 6][cc] = (rr >= 0 && rr < MMG) ? g_rudy[b][rr * MMG + cc] : 0.0f;
    }
    __syncthreads();

    const float g1[7] = {0.13533528f, 0.41111229f, 0.80073740f, 1.0f,
                         0.80073740f, 0.41111229f, 0.13533528f};
    float s1 = 0.0f;
#pragma unroll
    for (int i = 0; i < 7; i++) s1 += g1[i];
    const float inv_norm = __fdividef(1.0f, s1 * s1);

    const int lr = tid >> 6;       // 0..3
    const int j  = tid & 63;
    float s = 0.0f;
#pragma unroll
    for (int di = -3; di <= 3; di++) {
        float rs = 0.0f;
#pragma unroll
        for (int dj = -3; dj <= 3; dj++) {
            int jj = j + dj;
            if (jj >= 0 && jj < MMG)
                rs = fmaf(g1[dj + 3], tile[lr + 3 + di][jj], rs);
        }
        s = fmaf(g1[di + 3], rs, s);
    }
    s *= inv_norm;
    float ov = fmaxf(s - THRESH_F, 0.0f);
    float pen = ov * ov;

#pragma unroll
    for (int o = 16; o > 0; o >>= 1)
        pen += __shfl_xor_sync(0xffffffffu, pen, o);
    if ((tid & 31) == 0) red[tid >> 5] = pen;
    __syncthreads();
    if (tid == 0) {
        float v = 0.0f;
#pragma unroll
        for (int i = 0; i < 8; i++) v += red[i];
        atomicAdd(&g_pen[b], v);
        __threadfence();
        unsigned done = atomicAdd(&g_cnt[b], 1u);
        if (done == 15u) {
            __threadfence();
            float pp = *((volatile float*)&g_pen[b]);
            float h  = *((volatile float*)&g_hpwl[b]);
            out[b] = h + W_CONG_F * pp;
        }
    }
}

// ---------------------------------------------------------------------------
extern "C" void kernel_launch(void* const* d_in, const int* in_sizes, int n_in,
                              void* d_out, int out_size)
{
    const float* positions    = nullptr;
    const int*   net_to_pin   = nullptr;
    const int*   pin_to_macro = nullptr;
    const float* pin_offsets  = nullptr;
    const float* rot_onehot   = nullptr;
    const float* net_weights  = nullptr;

    for (int i = 0; i < n_in; i++) {
        switch (in_sizes[i]) {
            case BB * VV * 2:   positions    = (const float*)d_in[i]; break;
            case NNN * MPP:     net_to_pin   = (const int*)  d_in[i]; break;
            case PP:            pin_to_macro = (const int*)  d_in[i]; break;
            case PP * 2:        pin_offsets  = (const float*)d_in[i]; break;
            case BB * VV * 4:   rot_onehot   = (const float*)d_in[i]; break;
            case NNN:           net_weights  = (const float*)d_in[i]; break;
        }
    }

    macro_prep_kernel<<<(BB * VV + 255) / 256, 256>>>(positions, rot_onehot);
    pin_pos_kernel<<<(PP + 255) / 256, 256>>>(pin_to_macro, pin_offsets);
    net_kernel<<<dim3(NET_BLOCKS, BB), 256>>>(net_to_pin, net_weights);
    conv_kernel<<<dim3(16, BB), 256>>>((float*)d_out);
}

// round 10
// speedup vs baseline: 1.7989x; 1.7989x over previous
#include <cuda_runtime.h>
#include <math.h>

// Problem constants (match reference)
#define BB   4
#define VV   20000
#define PP   400000
#define NNN  50000
#define MPP  32
#define MMG  64            // grid M
#define THRESH_F 1.0f
#define W_CONG_F 0.5f

#define NET_BLOCKS 111     // 111*4 = 444 = 148 SMs * 3 blocks -> one wave

// log2(e) folded constants
#define GL2  14.426950408889634f   // GAMMA * log2(e),  GAMMA = 10
#define KL2  2.8853900817779268f   // K_SOFT * log2(e), K_SOFT = 2
#define LN2_OVER_GAMMA 0.069314718055994531f  // ln(2)/GAMMA
#define FPSCALE 33554432.0f        // 2^25 fixed-point scale for REDUX.SUM

// ---------------- scratch (device globals; no allocation allowed) ----------
__device__ float4 g_macro[BB * VV];            // {x, y, c, s} packed
__device__ float2 g_pin_pos[BB * PP];          // 12.8 MB
__device__ float  g_rudy[BB][MMG * MMG];       // 64 KB
__device__ float  g_hpwl[BB];
__device__ float  g_pen[BB];
__device__ unsigned g_cnt[BB];

// monotonic float <-> uint encoding for REDUX min/max on floats
__device__ __forceinline__ unsigned fenc(float x) {
    unsigned b = __float_as_uint(x);
    return b ^ (((unsigned)((int)b >> 31)) | 0x80000000u);
}
__device__ __forceinline__ float fdec(unsigned u) {
    unsigned b = u ^ ((~(unsigned)((int)u >> 31)) | 0x80000000u);
    return __uint_as_float(b);
}

__device__ __forceinline__ unsigned to_tf32(float x) {
    unsigned r;
    asm("cvt.rna.tf32.f32 %0, %1;" : "=r"(r) : "f"(x));
    return r;
}

__device__ __forceinline__ void mma_tf32(float& c0, float& c1, float& c2, float& c3,
                                         unsigned a0, unsigned a1, unsigned a2, unsigned a3,
                                         unsigned b0, unsigned b1) {
    asm volatile("mma.sync.aligned.m16n8k8.row.col.f32.tf32.tf32.f32 "
                 "{%0,%1,%2,%3}, {%4,%5,%6,%7}, {%8,%9}, {%0,%1,%2,%3};"
                 : "+f"(c0), "+f"(c1), "+f"(c2), "+f"(c3)
                 : "r"(a0), "r"(a1), "r"(a2), "r"(a3), "r"(b0), "r"(b1));
}

// ---------------------------------------------------------------------------
// Phase A0: pack {pos.x, pos.y, cos, sin} per (b, macro); zero accumulators.
__global__ __launch_bounds__(256) void macro_prep_kernel(
    const float* __restrict__ positions,      // (B,V,2)
    const float* __restrict__ rot_onehot)     // (B,V,4)
{
    int idx = blockIdx.x * blockDim.x + threadIdx.x;

    if (blockIdx.x < 64) {
        (&g_rudy[0][0])[idx] = 0.0f;
        if (idx < BB) { g_hpwl[idx] = 0.0f; g_pen[idx] = 0.0f; g_cnt[idx] = 0u; }
    }

    if (idx >= BB * VV) return;
    float2 pos = ((const float2*)positions)[idx];
    float4 oh  = ((const float4*)rot_onehot)[idx];
    g_macro[idx] = make_float4(pos.x, pos.y, oh.x - oh.z, oh.y - oh.w);
}

// ---------------------------------------------------------------------------
// Phase A: pin positions. One thread = one pin x 4 batches (single float4
// gather per batch; p2m/offsets loaded once; MLP=4).
__global__ __launch_bounds__(256) void pin_pos_kernel(
    const int*   __restrict__ pin_to_macro,   // (P,)
    const float* __restrict__ pin_offsets)    // (P,2)
{
    int p = blockIdx.x * blockDim.x + threadIdx.x;
    if (p >= PP) return;
    int m = pin_to_macro[p];
    float2 off = ((const float2*)pin_offsets)[p];

    float4 mac[BB];
#pragma unroll
    for (int b = 0; b < BB; b++) mac[b] = g_macro[b * VV + m];
#pragma unroll
    for (int b = 0; b < BB; b++) {
        float2 pp;
        pp.x = mac[b].x + mac[b].z * off.x - mac[b].w * off.y;
        pp.y = mac[b].y + mac[b].w * off.x + mac[b].z * off.y;
        g_pin_pos[b * PP + p] = pp;
    }
}

// ---------------------------------------------------------------------------
// Phase B: per-net soft-HPWL + bbox + rank-16 RUDY accumulation via tf32 MMA.
// 8 warps/block; each warp processes 2 nets per chunk (ILP) and owns a
// 16x32 region of the 64x64 output (4 m16n8k8 tiles).  [R4 structure]
__global__ __launch_bounds__(256) void net_kernel(
    const int*   __restrict__ net_to_pin,     // (NN,MP)
    const float* __restrict__ net_weights)    // (NN,)
{
    __shared__ unsigned XsT[MMG][17];   // [cell][k] tf32 bits, padded stride
    __shared__ unsigned YsT[MMG][17];

    const int b    = blockIdx.y;
    const int tid  = threadIdx.x;
    const int w    = tid >> 5;
    const int lane = tid & 31;
    const int g    = lane >> 2;      // group id 0..7
    const int tg   = lane & 3;       // thread-in-group 0..3
    const int rm   = (w & 3) * 16;   // warp's m (row) origin
    const int cn   = (w >> 2) * 32;  // warp's n (col) origin

    const int netsPerBlock = (NNN + NET_BLOCKS - 1) / NET_BLOCKS;   // 451
    const int n0 = blockIdx.x * netsPerBlock;
    const int n1 = min(n0 + netsPerBlock, NNN);

    // per-lane constant factors of the separable sigmoid exponentials
    float Cf[2], Df[2];
#pragma unroll
    for (int t = 0; t < 2; t++) {
        float gg = (float)(lane + t * 32);
        Cf[t] = exp2f(KL2 * (31.5f - gg));
        Df[t] = exp2f(KL2 * (gg - 32.0f));
    }

    float acc[4][4];   // [n-tile][c0..c3]
#pragma unroll
    for (int nt = 0; nt < 4; nt++)
#pragma unroll
        for (int c = 0; c < 4; c++) acc[nt][c] = 0.0f;

    float hp = 0.0f;   // meaningful on lane 0

    for (int base = n0; base < n1; base += 16) {
        float Fax[2], Fbx[2], Fay[2], Fby[2], ivbs[2];
        bool act[2];

#pragma unroll
        for (int q = 0; q < 2; q++) {
            const int n = base + w + q * 8;
            act[q] = (n < n1);
            Fax[q] = Fbx[q] = Fay[q] = Fby[q] = ivbs[q] = 0.0f;
            if (act[q]) {
                int j = net_to_pin[n * MPP + lane];
                bool valid = (j >= 0);
                int sj = j < 0 ? 0 : j;
                float2 pp = g_pin_pos[b * PP + sj];
                float px = pp.x, py = pp.y;

                unsigned ex = fenc(px);
                unsigned ey = fenc(py);
                float vxM = fdec(__reduce_max_sync(0xffffffffu, valid ? ex : 0u));
                float vxm = fdec(__reduce_min_sync(0xffffffffu, valid ? ex : 0xffffffffu));
                float vyM = fdec(__reduce_max_sync(0xffffffffu, valid ? ey : 0u));
                float vym = fdec(__reduce_min_sync(0xffffffffu, valid ? ey : 0xffffffffu));

                // LSE sums via fixed-point REDUX.SUM (terms in [0,1];
                // invalid lanes contribute exactly 0, matching reference)
                float exM = valid ? exp2f( GL2 * (px - vxM)) : 0.0f;
                float exm = valid ? exp2f(-GL2 * (px - vxm)) : 0.0f;
                float eyM = valid ? exp2f( GL2 * (py - vyM)) : 0.0f;
                float eym = valid ? exp2f(-GL2 * (py - vym)) : 0.0f;
                unsigned sxM = __reduce_add_sync(0xffffffffu, (unsigned)__float2uint_rn(exM * FPSCALE));
                unsigned sxm = __reduce_add_sync(0xffffffffu, (unsigned)__float2uint_rn(exm * FPSCALE));
                unsigned syM = __reduce_add_sync(0xffffffffu, (unsigned)__float2uint_rn(eyM * FPSCALE));
                unsigned sym = __reduce_add_sync(0xffffffffu, (unsigned)__float2uint_rn(eym * FPSCALE));

                if (lane == 0) {
                    // log2 of product of the 4 scaled sums; remove 4*25 bias
                    float prod = ((float)sxM * (float)sxm) *
                                 ((float)syM * (float)sym);
                    float wl = (vxM - vxm) + (vyM - vym)
                             + (__log2f(prod) - 100.0f) * LN2_OVER_GAMMA;
                    hp += wl * net_weights[n];
                }

                float bxm = (vxm + 1.0f) * 0.5f * (MMG - 1);
                float bxM = (vxM + 1.0f) * 0.5f * (MMG - 1);
                float bym = (vym + 1.0f) * 0.5f * (MMG - 1);
                float byM = (vyM + 1.0f) * 0.5f * (MMG - 1);
                float bsize = fmaxf((bxM - bxm + 1.0f) * (byM - bym + 1.0f), 1.0f);
                ivbs[q] = __fdividef(1.0f, bsize);

                Fax[q] = exp2f(KL2 * (bxm - 32.0f));
                Fbx[q] = exp2f(KL2 * (31.5f - bxM));
                Fay[q] = exp2f(KL2 * (bym - 32.0f));
                Fby[q] = exp2f(KL2 * (31.5f - byM));
            }
        }

#pragma unroll
        for (int t = 0; t < 2; t++) {
            const int gi = lane + t * 32;
#pragma unroll
            for (int q = 0; q < 2; q++) {
                float xv = 0.0f, yv = 0.0f;
                if (act[q]) {
                    float ex0 = fminf(Fax[q] * Cf[t], 1e18f);
                    float ex1 = fminf(Fbx[q] * Df[t], 1e18f);
                    float ey0 = fminf(Fay[q] * Cf[t], 1e18f);
                    float ey1 = fminf(Fby[q] * Df[t], 1e18f);
                    float Px = (1.0f + ex0) * (1.0f + ex1);
                    float Py = (1.0f + ey0) * (1.0f + ey1);
                    float R  = __fdividef(1.0f, Px * Py);
                    xv = Py * R;
                    yv = ivbs[q] * Px * R;
                }
                XsT[gi][w + q * 8] = to_tf32(xv);
                YsT[gi][w + q * 8] = to_tf32(yv);
            }
        }
        __syncthreads();

        // rank-16 update: D[i][j] += sum_k Y[k][i] * X[k][j]
#pragma unroll
        for (int ks = 0; ks < 2; ks++) {
            const int k0 = ks * 8;
            unsigned a0 = YsT[rm + g    ][k0 + tg    ];
            unsigned a1 = YsT[rm + g + 8][k0 + tg    ];
            unsigned a2 = YsT[rm + g    ][k0 + tg + 4];
            unsigned a3 = YsT[rm + g + 8][k0 + tg + 4];
#pragma unroll
            for (int nt = 0; nt < 4; nt++) {
                unsigned b0 = XsT[cn + nt * 8 + g][k0 + tg    ];
                unsigned b1 = XsT[cn + nt * 8 + g][k0 + tg + 4];
                mma_tf32(acc[nt][0], acc[nt][1], acc[nt][2], acc[nt][3],
                         a0, a1, a2, a3, b0, b1);
            }
        }
        __syncthreads();
    }

    // writeback: c0 (r, 2tg), c1 (r, 2tg+1), c2 (r+8, 2tg), c3 (r+8, 2tg+1)
    {
        const int r0 = rm + g;
        const int r1 = rm + g + 8;
#pragma unroll
        for (int nt = 0; nt < 4; nt++) {
            const int col = cn + nt * 8 + 2 * tg;
            atomicAdd(&g_rudy[b][r0 * MMG + col    ], acc[nt][0]);
            atomicAdd(&g_rudy[b][r0 * MMG + col + 1], acc[nt][1]);
            atomicAdd(&g_rudy[b][r1 * MMG + col    ], acc[nt][2]);
            atomicAdd(&g_rudy[b][r1 * MMG + col + 1], acc[nt][3]);
        }
    }

    if (lane == 0) atomicAdd(&g_hpwl[b], hp);
}

// ---------------------------------------------------------------------------
// Phase C: 7x7 Gaussian smooth (zero-padded) + overflow penalty + finalize.
__global__ __launch_bounds__(256) void conv_kernel(float* __restrict__ out)
{
    __shared__ float tile[10][MMG];
    __shared__ float red[8];
    const int b     = blockIdx.y;
    const int slice = blockIdx.x;
    const int tid   = threadIdx.x;
    const int r0    = slice * 4;

    for (int i = tid; i < 10 * MMG; i += 256) {
        int rr = r0 - 3 + (i >> 6);
        int cc = i & 63;
        tile[i >> 6][cc] = (rr >= 0 && rr < MMG) ? g_rudy[b][rr * MMG + cc] : 0.0f;
    }
    __syncthreads();

    const float g1[7] = {0.13533528f, 0.41111229f, 0.80073740f, 1.0f,
                         0.80073740f, 0.41111229f, 0.13533528f};
    float s1 = 0.0f;
#pragma unroll
    for (int i = 0; i < 7; i++) s1 += g1[i];
    const float inv_norm = __fdividef(1.0f, s1 * s1);

    const int lr = tid >> 6;       // 0..3
    const int j  = tid & 63;
    float s = 0.0f;
#pragma unroll
    for (int di = -3; di <= 3; di++) {
        float rs = 0.0f;
#pragma unroll
        for (int dj = -3; dj <= 3; dj++) {
            int jj = j + dj;
            if (jj >= 0 && jj < MMG)
                rs = fmaf(g1[dj + 3], tile[lr + 3 + di][jj], rs);
        }
        s = fmaf(g1[di + 3], rs, s);
    }
    s *= inv_norm;
    float ov = fmaxf(s - THRESH_F, 0.0f);
    float pen = ov * ov;

#pragma unroll
    for (int o = 16; o > 0; o >>= 1)
        pen += __shfl_xor_sync(0xffffffffu, pen, o);
    if ((tid & 31) == 0) red[tid >> 5] = pen;
    __syncthreads();
    if (tid == 0) {
        float v = 0.0f;
#pragma unroll
        for (int i = 0; i < 8; i++) v += red[i];
        atomicAdd(&g_pen[b], v);
        __threadfence();
        unsigned done = atomicAdd(&g_cnt[b], 1u);
        if (done == 15u) {
            __threadfence();
            float pp = *((volatile float*)&g_pen[b]);
            float h  = *((volatile float*)&g_hpwl[b]);
            out[b] = h + W_CONG_F * pp;
        }
    }
}

// ---------------------------------------------------------------------------
extern "C" void kernel_launch(void* const* d_in, const int* in_sizes, int n_in,
                              void* d_out, int out_size)
{
    const float* positions    = nullptr;
    const int*   net_to_pin   = nullptr;
    const int*   pin_to_macro = nullptr;
    const float* pin_offsets  = nullptr;
    const float* rot_onehot   = nullptr;
    const float* net_weights  = nullptr;

    for (int i = 0; i < n_in; i++) {
        switch (in_sizes[i]) {
            case BB * VV * 2:   positions    = (const float*)d_in[i]; break;
            case NNN * MPP:     net_to_pin   = (const int*)  d_in[i]; break;
            case PP:            pin_to_macro = (const int*)  d_in[i]; break;
            case PP * 2:        pin_offsets  = (const float*)d_in[i]; break;
            case BB * VV * 4:   rot_onehot   = (const float*)d_in[i]; break;
            case NNN:           net_weights  = (const float*)d_in[i]; break;
        }
    }

    macro_prep_kernel<<<(BB * VV + 255) / 256, 256>>>(positions, rot_onehot);
    pin_pos_kernel<<<(PP + 255) / 256, 256>>>(pin_to_macro, pin_offsets);
    net_kernel<<<dim3(NET_BLOCKS, BB), 256>>>(net_to_pin, net_weights);
    conv_kernel<<<dim3(16, BB), 256>>>((float*)d_out);
}

// round 11
// speedup vs baseline: 1.8551x; 1.0312x over previous
#include <cuda_runtime.h>
#include <cuda_fp16.h>
#include <math.h>

// Problem constants (match reference)
#define BB   4
#define VV   20000
#define PP   400000
#define NNN  50000
#define MPP  32
#define MMG  64            // grid M
#define THRESH_F 1.0f
#define W_CONG_F 0.5f

#define NET_BLOCKS 148     // grid (148, 2) = 296 blocks = one wave at 2/SM

// log2(e) folded constants
#define GL2  14.426950408889634f   // GAMMA * log2(e),  GAMMA = 10
#define KL2  2.8853900817779268f   // K_SOFT * log2(e), K_SOFT = 2
#define LN2_OVER_GAMMA 0.069314718055994531f  // ln(2)/GAMMA
#define FPSCALE 33554432.0f        // 2^25 fixed-point scale for REDUX.SUM

// ---------------- scratch (device globals; no allocation allowed) ----------
__device__ float4  g_macro[BB * VV];           // {x, y, c, s} packed
__device__ __half2 g_pin_posH[PP * 4];         // [pin][batch] {x,y} fp16, 16B/pin
__device__ float   g_rudy[BB][MMG * MMG];      // 64 KB
__device__ float   g_hpwl[BB];
__device__ float   g_pen[BB];
__device__ unsigned g_cnt[BB];

// monotonic float <-> uint encoding for REDUX min/max on floats
__device__ __forceinline__ unsigned fenc(float x) {
    unsigned b = __float_as_uint(x);
    return b ^ (((unsigned)((int)b >> 31)) | 0x80000000u);
}
__device__ __forceinline__ float fdec(unsigned u) {
    unsigned b = u ^ ((~(unsigned)((int)u >> 31)) | 0x80000000u);
    return __uint_as_float(b);
}

__device__ __forceinline__ unsigned to_tf32(float x) {
    unsigned r;
    asm("cvt.rna.tf32.f32 %0, %1;" : "=r"(r) : "f"(x));
    return r;
}

__device__ __forceinline__ void mma_tf32(float& c0, float& c1, float& c2, float& c3,
                                         unsigned a0, unsigned a1, unsigned a2, unsigned a3,
                                         unsigned b0, unsigned b1) {
    asm volatile("mma.sync.aligned.m16n8k8.row.col.f32.tf32.tf32.f32 "
                 "{%0,%1,%2,%3}, {%4,%5,%6,%7}, {%8,%9}, {%0,%1,%2,%3};"
                 : "+f"(c0), "+f"(c1), "+f"(c2), "+f"(c3)
                 : "r"(a0), "r"(a1), "r"(a2), "r"(a3), "r"(b0), "r"(b1));
}

// ---------------------------------------------------------------------------
// Phase A0: pack {pos.x, pos.y, cos, sin} per (b, macro); zero accumulators.
__global__ __launch_bounds__(256) void macro_prep_kernel(
    const float* __restrict__ positions,      // (B,V,2)
    const float* __restrict__ rot_onehot)     // (B,V,4)
{
    int idx = blockIdx.x * blockDim.x + threadIdx.x;

    if (blockIdx.x < 64) {
        (&g_rudy[0][0])[idx] = 0.0f;
        if (idx < BB) { g_hpwl[idx] = 0.0f; g_pen[idx] = 0.0f; g_cnt[idx] = 0u; }
    }

    if (idx >= BB * VV) return;
    float2 pos = ((const float2*)positions)[idx];
    float4 oh  = ((const float4*)rot_onehot)[idx];
    g_macro[idx] = make_float4(pos.x, pos.y, oh.x - oh.z, oh.y - oh.w);
}

// ---------------------------------------------------------------------------
// Phase A: pin positions. One thread = one pin x 4 batches; packs all four
// batches' {x,y} as fp16 into one 16-byte word (single STG.128).
__global__ __launch_bounds__(256) void pin_pos_kernel(
    const int*   __restrict__ pin_to_macro,   // (P,)
    const float* __restrict__ pin_offsets)    // (P,2)
{
    int p = blockIdx.x * blockDim.x + threadIdx.x;
    if (p >= PP) return;
    int m = pin_to_macro[p];
    float2 off = ((const float2*)pin_offsets)[p];

    float4 mac[BB];
#pragma unroll
    for (int b = 0; b < BB; b++) mac[b] = g_macro[b * VV + m];

    __half2 h[BB];
#pragma unroll
    for (int b = 0; b < BB; b++) {
        float x = mac[b].x + mac[b].z * off.x - mac[b].w * off.y;
        float y = mac[b].y + mac[b].w * off.x + mac[b].z * off.y;
        h[b] = __float22half2_rn(make_float2(x, y));
    }
    ((float4*)g_pin_posH)[p] = *(float4*)h;
}

// ---------------------------------------------------------------------------
// Phase B: per-net soft-HPWL + bbox + rank-16 RUDY accumulation via tf32 MMA.
// grid (148, 2): block (x, bp) handles its net range for batches {2bp, 2bp+1}.
// One divergent LDG.64 per (net,lane) serves BOTH batches.
// 8 warps; each warp: 2 nets x 2 batches scalar, then 16x64 of its batch's
// 64x64 output (8 m16n8 tiles, acc 32 regs).
__global__ __launch_bounds__(256) void net_kernel(
    const int*   __restrict__ net_to_pin,     // (NN,MP)
    const float* __restrict__ net_weights)    // (NN,)
{
    __shared__ unsigned XsT[2][MMG][17];   // [batch-in-pair][cell][k]
    __shared__ unsigned YsT[2][MMG][17];

    const int bp   = blockIdx.y;     // batch pair 0 -> {0,1}, 1 -> {2,3}
    const int tid  = threadIdx.x;
    const int w    = tid >> 5;
    const int lane = tid & 31;
    const int g    = lane >> 2;      // group id 0..7
    const int tg   = lane & 3;       // thread-in-group 0..3
    const int we   = w >> 2;         // warp's batch-in-pair (MMA stage)
    const int rm   = (w & 3) * 16;   // warp's m (row) origin (MMA stage)

    const int netsPerBlock = (NNN + NET_BLOCKS - 1) / NET_BLOCKS;   // 338
    const int n0 = blockIdx.x * netsPerBlock;
    const int n1 = min(n0 + netsPerBlock, NNN);

    // per-lane constant factors of the separable sigmoid exponentials
    float Cf[2], Df[2];
#pragma unroll
    for (int t = 0; t < 2; t++) {
        float gg = (float)(lane + t * 32);
        Cf[t] = exp2f(KL2 * (31.5f - gg));
        Df[t] = exp2f(KL2 * (gg - 32.0f));
    }

    float acc[8][4];   // [n-tile][c0..c3]  (16 rows x 64 cols of one batch)
#pragma unroll
    for (int nt = 0; nt < 8; nt++)
#pragma unroll
        for (int c = 0; c < 4; c++) acc[nt][c] = 0.0f;

    float hp2[2] = {0.0f, 0.0f};   // meaningful on lane 0, per batch-in-pair

    for (int base = n0; base < n1; base += 16) {
        float Fax[2][2], Fbx[2][2], Fay[2][2], Fby[2][2], ivbs[2][2];
        bool act[2];

#pragma unroll
        for (int q = 0; q < 2; q++) {
            const int n = base + w + q * 8;
            act[q] = (n < n1);
#pragma unroll
            for (int e = 0; e < 2; e++) {
                Fax[q][e] = Fbx[q][e] = Fay[q][e] = Fby[q][e] = ivbs[q][e] = 0.0f;
            }
            if (act[q]) {
                int j = net_to_pin[n * MPP + lane];
                bool valid = (j >= 0);
                int sj = j < 0 ? 0 : j;
                // ONE 8-byte gather -> both batches of the pair
                uint2 pv = ((const uint2*)g_pin_posH)[sj * 2 + bp];

#pragma unroll
                for (int e = 0; e < 2; e++) {
                    float2 pf = __half22float2(
                        *(const __half2*)(e == 0 ? &pv.x : &pv.y));
                    float px = pf.x, py = pf.y;

                    unsigned ex = fenc(px);
                    unsigned ey = fenc(py);
                    float vxM = fdec(__reduce_max_sync(0xffffffffu, valid ? ex : 0u));
                    float vxm = fdec(__reduce_min_sync(0xffffffffu, valid ? ex : 0xffffffffu));
                    float vyM = fdec(__reduce_max_sync(0xffffffffu, valid ? ey : 0u));
                    float vym = fdec(__reduce_min_sync(0xffffffffu, valid ? ey : 0xffffffffu));

                    // LSE sums via fixed-point REDUX.SUM (terms in [0,1];
                    // invalid lanes contribute exactly 0, matching reference)
                    float exM = valid ? exp2f( GL2 * (px - vxM)) : 0.0f;
                    float exm = valid ? exp2f(-GL2 * (px - vxm)) : 0.0f;
                    float eyM = valid ? exp2f( GL2 * (py - vyM)) : 0.0f;
                    float eym = valid ? exp2f(-GL2 * (py - vym)) : 0.0f;
                    unsigned sxM = __reduce_add_sync(0xffffffffu, (unsigned)__float2uint_rn(exM * FPSCALE));
                    unsigned sxm = __reduce_add_sync(0xffffffffu, (unsigned)__float2uint_rn(exm * FPSCALE));
                    unsigned syM = __reduce_add_sync(0xffffffffu, (unsigned)__float2uint_rn(eyM * FPSCALE));
                    unsigned sym = __reduce_add_sync(0xffffffffu, (unsigned)__float2uint_rn(eym * FPSCALE));

                    if (lane == 0) {
                        float prod = ((float)sxM * (float)sxm) *
                                     ((float)syM * (float)sym);
                        float wl = (vxM - vxm) + (vyM - vym)
                                 + (__log2f(prod) - 100.0f) * LN2_OVER_GAMMA;
                        hp2[e] += wl * net_weights[n];
                    }

                    float bxm = (vxm + 1.0f) * 0.5f * (MMG - 1);
                    float bxM = (vxM + 1.0f) * 0.5f * (MMG - 1);
                    float bym = (vym + 1.0f) * 0.5f * (MMG - 1);
                    float byM = (vyM + 1.0f) * 0.5f * (MMG - 1);
                    float bsize = fmaxf((bxM - bxm + 1.0f) * (byM - bym + 1.0f), 1.0f);
                    ivbs[q][e] = __fdividef(1.0f, bsize);

                    Fax[q][e] = exp2f(KL2 * (bxm - 32.0f));
                    Fbx[q][e] = exp2f(KL2 * (31.5f - bxM));
                    Fay[q][e] = exp2f(KL2 * (bym - 32.0f));
                    Fby[q][e] = exp2f(KL2 * (31.5f - byM));
                }
            }
        }

#pragma unroll
        for (int t = 0; t < 2; t++) {
            const int gi = lane + t * 32;
#pragma unroll
            for (int q = 0; q < 2; q++) {
#pragma unroll
                for (int e = 0; e < 2; e++) {
                    float xv = 0.0f, yv = 0.0f;
                    if (act[q]) {
                        float ex0 = fminf(Fax[q][e] * Cf[t], 1e18f);
                        float ex1 = fminf(Fbx[q][e] * Df[t], 1e18f);
                        float ey0 = fminf(Fay[q][e] * Cf[t], 1e18f);
                        float ey1 = fminf(Fby[q][e] * Df[t], 1e18f);
                        float Px = (1.0f + ex0) * (1.0f + ex1);
                        float Py = (1.0f + ey0) * (1.0f + ey1);
                        float R  = __fdividef(1.0f, Px * Py);
                        xv = Py * R;
                        yv = ivbs[q][e] * Px * R;
                    }
                    XsT[e][gi][w + q * 8] = to_tf32(xv);
                    YsT[e][gi][w + q * 8] = to_tf32(yv);
                }
            }
        }
        __syncthreads();

        // rank-16 update of this warp's batch: D[i][j] += sum_k Y[k][i]*X[k][j]
#pragma unroll
        for (int ks = 0; ks < 2; ks++) {
            const int k0 = ks * 8;
            unsigned a0 = YsT[we][rm + g    ][k0 + tg    ];
            unsigned a1 = YsT[we][rm + g + 8][k0 + tg    ];
            unsigned a2 = YsT[we][rm + g    ][k0 + tg + 4];
            unsigned a3 = YsT[we][rm + g + 8][k0 + tg + 4];
#pragma unroll
            for (int nt = 0; nt < 8; nt++) {
                unsigned b0 = XsT[we][nt * 8 + g][k0 + tg    ];
                unsigned b1 = XsT[we][nt * 8 + g][k0 + tg + 4];
                mma_tf32(acc[nt][0], acc[nt][1], acc[nt][2], acc[nt][3],
                         a0, a1, a2, a3, b0, b1);
            }
        }
        __syncthreads();
    }

    // writeback: warp's batch is 2*bp + we
    {
        const int bg = 2 * bp + we;
        const int r0 = rm + g;
        const int r1 = rm + g + 8;
#pragma unroll
        for (int nt = 0; nt < 8; nt++) {
            const int col = nt * 8 + 2 * tg;
            atomicAdd(&g_rudy[bg][r0 * MMG + col    ], acc[nt][0]);
            atomicAdd(&g_rudy[bg][r0 * MMG + col + 1], acc[nt][1]);
            atomicAdd(&g_rudy[bg][r1 * MMG + col    ], acc[nt][2]);
            atomicAdd(&g_rudy[bg][r1 * MMG + col + 1], acc[nt][3]);
        }
    }

    if (lane == 0) {
        atomicAdd(&g_hpwl[2 * bp    ], hp2[0]);
        atomicAdd(&g_hpwl[2 * bp + 1], hp2[1]);
    }
}

// ---------------------------------------------------------------------------
// Phase C: 7x7 Gaussian smooth (zero-padded) + overflow penalty + finalize.
__global__ __launch_bounds__(256) void conv_kernel(float* __restrict__ out)
{
    __shared__ float tile[10][MMG];
    __shared__ float red[8];
    const int b     = blockIdx.y;
    const int slice = blockIdx.x;
    const int tid   = threadIdx.x;
    const int r0    = slice * 4;

    for (int i = tid; i < 10 * MMG; i += 256) {
        int rr = r0 - 3 + (i >> 6);
        int cc = i & 63;
        tile[i >> 6][cc] = (rr >= 0 && rr < MMG) ? g_rudy[b][rr * MMG + cc] : 0.0f;
    }
    __syncthreads();

    const float g1[7] = {0.13533528f, 0.41111229f, 0.80073740f, 1.0f,
                         0.80073740f, 0.41111229f, 0.13533528f};
    float s1 = 0.0f;
#pragma unroll
    for (int i = 0; i < 7; i++) s1 += g1[i];
    const float inv_norm = __fdividef(1.0f, s1 * s1);

    const int lr = tid >> 6;       // 0..3
    const int j  = tid & 63;
    float s = 0.0f;
#pragma unroll
    for (int di = -3; di <= 3; di++) {
        float rs = 0.0f;
#pragma unroll
        for (int dj = -3; dj <= 3; dj++) {
            int jj = j + dj;
            if (jj >= 0 && jj < MMG)
                rs = fmaf(g1[dj + 3], tile[lr + 3 + di][jj], rs);
        }
        s = fmaf(g1[di + 3], rs, s);
    }
    s *= inv_norm;
    float ov = fmaxf(s - THRESH_F, 0.0f);
    float pen = ov * ov;

#pragma unroll
    for (int o = 16; o > 0; o >>= 1)
        pen += __shfl_xor_sync(0xffffffffu, pen, o);
    if ((tid & 31) == 0) red[tid >> 5] = pen;
    __syncthreads();
    if (tid == 0) {
        float v = 0.0f;
#pragma unroll
        for (int i = 0; i < 8; i++) v += red[i];
        atomicAdd(&g_pen[b], v);
        __threadfence();
        unsigned done = atomicAdd(&g_cnt[b], 1u);
        if (done == 15u) {
            __threadfence();
            float pp = *((volatile float*)&g_pen[b]);
            float h  = *((volatile float*)&g_hpwl[b]);
            out[b] = h + W_CONG_F * pp;
        }
    }
}

// ---------------------------------------------------------------------------
extern "C" void kernel_launch(void* const* d_in, const int* in_sizes, int n_in,
                              void* d_out, int out_size)
{
    const float* positions    = nullptr;
    const int*   net_to_pin   = nullptr;
    const int*   pin_to_macro = nullptr;
    const float* pin_offsets  = nullptr;
    const float* rot_onehot   = nullptr;
    const float* net_weights  = nullptr;

    for (int i = 0; i < n_in; i++) {
        switch (in_sizes[i]) {
            case BB * VV * 2:   positions    = (const float*)d_in[i]; break;
            case NNN * MPP:     net_to_pin   = (const int*)  d_in[i]; break;
            case PP:            pin_to_macro = (const int*)  d_in[i]; break;
            case PP * 2:        pin_offsets  = (const float*)d_in[i]; break;
            case BB * VV * 4:   rot_onehot   = (const float*)d_in[i]; break;
            case NNN:           net_weights  = (const float*)d_in[i]; break;
        }
    }

    macro_prep_kernel<<<(BB * VV + 255) / 256, 256>>>(positions, rot_onehot);
    pin_pos_kernel<<<(PP + 255) / 256, 256>>>(pin_to_macro, pin_offsets);
    net_kernel<<<dim3(NET_BLOCKS, 2), 256>>>(net_to_pin, net_weights);
    conv_kernel<<<dim3(16, BB), 256>>>((float*)d_out);
}

// round 13
// speedup vs baseline: 2.0284x; 1.0934x over previous
#include <cuda_runtime.h>
#include <cuda_fp16.h>
#include <math.h>

// Problem constants (match reference)
#define BB   4
#define VV   20000
#define PP   400000
#define NNN  50000
#define MPP  32
#define MMG  64            // grid M
#define THRESH_F 1.0f
#define W_CONG_F 0.5f

#define NET_BLOCKS 148     // grid (148, 2) = 296 blocks = one wave at 2/SM

// log2(e) folded constants
#define GL2  14.426950408889634f   // GAMMA * log2(e),  GAMMA = 10
#define KL2  2.8853900817779268f   // K_SOFT * log2(e), K_SOFT = 2
#define LN2_OVER_GAMMA 0.069314718055994531f  // ln(2)/GAMMA
#define FPSCALE 33554432.0f        // 2^25 fixed-point scale for REDUX.SUM

// ---------------- scratch (device globals; no allocation allowed) ----------
__device__ float4  g_macro[BB * VV];           // {x, y, c, s} packed
__device__ __half2 g_pin_posH[PP * 4];         // [pin][batch] {x,y} fp16, 16B/pin
__device__ float   g_rudy[BB][MMG * MMG];      // 64 KB
__device__ float   g_hpwl[BB];
__device__ float   g_pen[BB];
__device__ unsigned g_cnt[BB];

// monotonic float <-> uint encoding for REDUX min/max on floats
__device__ __forceinline__ unsigned fenc(float x) {
    unsigned b = __float_as_uint(x);
    return b ^ (((unsigned)((int)b >> 31)) | 0x80000000u);
}
__device__ __forceinline__ float fdec(unsigned u) {
    unsigned b = u ^ ((~(unsigned)((int)u >> 31)) | 0x80000000u);
    return __uint_as_float(b);
}

__device__ __forceinline__ unsigned to_tf32(float x) {
    unsigned r;
    asm("cvt.rna.tf32.f32 %0, %1;" : "=r"(r) : "f"(x));
    return r;
}

__device__ __forceinline__ void mma_tf32(float& c0, float& c1, float& c2, float& c3,
                                         unsigned a0, unsigned a1, unsigned a2, unsigned a3,
                                         unsigned b0, unsigned b1) {
    asm volatile("mma.sync.aligned.m16n8k8.row.col.f32.tf32.tf32.f32 "
                 "{%0,%1,%2,%3}, {%4,%5,%6,%7}, {%8,%9}, {%0,%1,%2,%3};"
                 : "+f"(c0), "+f"(c1), "+f"(c2), "+f"(c3)
                 : "r"(a0), "r"(a1), "r"(a2), "r"(a3), "r"(b0), "r"(b1));
}

// ---------------------------------------------------------------------------
// Phase A0: pack {pos.x, pos.y, cos, sin} per (b, macro); zero accumulators.
__global__ __launch_bounds__(256) void macro_prep_kernel(
    const float* __restrict__ positions,      // (B,V,2)
    const float* __restrict__ rot_onehot)     // (B,V,4)
{
    int idx = blockIdx.x * blockDim.x + threadIdx.x;

    if (blockIdx.x < 64) {
        (&g_rudy[0][0])[idx] = 0.0f;
        if (idx < BB) { g_hpwl[idx] = 0.0f; g_pen[idx] = 0.0f; g_cnt[idx] = 0u; }
    }

    if (idx >= BB * VV) return;
    float2 pos = ((const float2*)positions)[idx];
    float4 oh  = ((const float4*)rot_onehot)[idx];
    g_macro[idx] = make_float4(pos.x, pos.y, oh.x - oh.z, oh.y - oh.w);
}

// ---------------------------------------------------------------------------
// Phase A: pin positions. One thread = one pin x 4 batches; packs all four
// batches' {x,y} as fp16 into one 16-byte word (single STG.128).
__global__ __launch_bounds__(256) void pin_pos_kernel(
    const int*   __restrict__ pin_to_macro,   // (P,)
    const float* __restrict__ pin_offsets)    // (P,2)
{
    int p = blockIdx.x * blockDim.x + threadIdx.x;
    if (p >= PP) return;
    int m = pin_to_macro[p];
    float2 off = ((const float2*)pin_offsets)[p];

    float4 mac[BB];
#pragma unroll
    for (int b = 0; b < BB; b++) mac[b] = g_macro[b * VV + m];

    __half2 h[BB];
#pragma unroll
    for (int b = 0; b < BB; b++) {
        float x = mac[b].x + mac[b].z * off.x - mac[b].w * off.y;
        float y = mac[b].y + mac[b].w * off.x + mac[b].z * off.y;
        h[b] = __float22half2_rn(make_float2(x, y));
    }
    ((float4*)g_pin_posH)[p] = *(float4*)h;
}

// ---------------------------------------------------------------------------
// Phase B: per-net soft-HPWL + bbox + rank-16 RUDY accumulation via tf32 MMA.
// grid (148, 2): block (x, bp) handles its net range for batches {2bp, 2bp+1}.
// Software-pipelined: next chunk's indices prefetched at scalar-phase start,
// next chunk's pin gather issued right after current pins are consumed.
__global__ __launch_bounds__(256) void net_kernel(
    const int*   __restrict__ net_to_pin,     // (NN,MP)
    const float* __restrict__ net_weights)    // (NN,)
{
    __shared__ unsigned XsT[2][MMG][17];   // [batch-in-pair][cell][k]
    __shared__ unsigned YsT[2][MMG][17];

    const int bp   = blockIdx.y;     // batch pair 0 -> {0,1}, 1 -> {2,3}
    const int tid  = threadIdx.x;
    const int w    = tid >> 5;
    const int lane = tid & 31;
    const int g    = lane >> 2;      // group id 0..7
    const int tg   = lane & 3;       // thread-in-group 0..3
    const int we   = w >> 2;         // warp's batch-in-pair (MMA stage)
    const int rm   = (w & 3) * 16;   // warp's m (row) origin (MMA stage)

    const int netsPerBlock = (NNN + NET_BLOCKS - 1) / NET_BLOCKS;   // 338
    const int n0 = blockIdx.x * netsPerBlock;
    const int n1 = min(n0 + netsPerBlock, NNN);

    // per-lane constant factors of the separable sigmoid exponentials
    float Cf[2], Df[2];
#pragma unroll
    for (int t = 0; t < 2; t++) {
        float gg = (float)(lane + t * 32);
        Cf[t] = exp2f(KL2 * (31.5f - gg));
        Df[t] = exp2f(KL2 * (gg - 32.0f));
    }

    float acc[8][4];   // [n-tile][c0..c3]  (16 rows x 64 cols of one batch)
#pragma unroll
    for (int nt = 0; nt < 8; nt++)
#pragma unroll
        for (int c = 0; c < 4; c++) acc[nt][c] = 0.0f;

    float hp2[2] = {0.0f, 0.0f};   // meaningful on lane 0, per batch-in-pair

    // ---- pipeline prologue: indices + pins for first chunk ----
    int   jc[2];
    uint2 pvc[2];
#pragma unroll
    for (int q = 0; q < 2; q++) {
        const int n = n0 + w + q * 8;
        jc[q] = (n < n1) ? net_to_pin[n * MPP + lane] : -1;
    }
#pragma unroll
    for (int q = 0; q < 2; q++) {
        int sj = jc[q] < 0 ? 0 : jc[q];
        pvc[q] = ((const uint2*)g_pin_posH)[sj * 2 + bp];
    }

    for (int base = n0; base < n1; base += 16) {
        const int basen = base + 16;

        // ---- prefetch next chunk's indices (consumed mid-chunk) ----
        int jn[2];
#pragma unroll
        for (int q = 0; q < 2; q++) {
            const int nn = basen + w + q * 8;
            jn[q] = (basen < n1 && nn < n1) ? net_to_pin[nn * MPP + lane] : -1;
        }

        float Fax[2][2], Fbx[2][2], Fay[2][2], Fby[2][2], ivbs[2][2];
        bool act[2];

#pragma unroll
        for (int q = 0; q < 2; q++) {
            const int n = base + w + q * 8;
            act[q] = (n < n1);
#pragma unroll
            for (int e = 0; e < 2; e++) {
                Fax[q][e] = Fbx[q][e] = Fay[q][e] = Fby[q][e] = ivbs[q][e] = 0.0f;
            }
            if (act[q]) {
                bool valid = (jc[q] >= 0);
                uint2 pv = pvc[q];

#pragma unroll
                for (int e = 0; e < 2; e++) {
                    float2 pf = __half22float2(
                        *(const __half2*)(e == 0 ? &pv.x : &pv.y));
                    float px = pf.x, py = pf.y;

                    unsigned ex = fenc(px);
                    unsigned ey = fenc(py);
                    float vxM = fdec(__reduce_max_sync(0xffffffffu, valid ? ex : 0u));
                    float vxm = fdec(__reduce_min_sync(0xffffffffu, valid ? ex : 0xffffffffu));
                    float vyM = fdec(__reduce_max_sync(0xffffffffu, valid ? ey : 0u));
                    float vym = fdec(__reduce_min_sync(0xffffffffu, valid ? ey : 0xffffffffu));

                    // LSE sums via fixed-point REDUX.SUM (terms in [0,1];
                    // invalid lanes contribute exactly 0, matching reference)
                    float exM = valid ? exp2f( GL2 * (px - vxM)) : 0.0f;
                    float exm = valid ? exp2f(-GL2 * (px - vxm)) : 0.0f;
                    float eyM = valid ? exp2f( GL2 * (py - vyM)) : 0.0f;
                    float eym = valid ? exp2f(-GL2 * (py - vym)) : 0.0f;
                    unsigned sxM = __reduce_add_sync(0xffffffffu, (unsigned)__float2uint_rn(exM * FPSCALE));
                    unsigned sxm = __reduce_add_sync(0xffffffffu, (unsigned)__float2uint_rn(exm * FPSCALE));
                    unsigned syM = __reduce_add_sync(0xffffffffu, (unsigned)__float2uint_rn(eyM * FPSCALE));
                    unsigned sym = __reduce_add_sync(0xffffffffu, (unsigned)__float2uint_rn(eym * FPSCALE));

                    if (lane == 0) {
                        float prod = ((float)sxM * (float)sxm) *
                                     ((float)syM * (float)sym);
                        float wl = (vxM - vxm) + (vyM - vym)
                                 + (__log2f(prod) - 100.0f) * LN2_OVER_GAMMA;
                        hp2[e] += wl * net_weights[n];
                    }

                    float bxm = (vxm + 1.0f) * 0.5f * (MMG - 1);
                    float bxM = (vxM + 1.0f) * 0.5f * (MMG - 1);
                    float bym = (vym + 1.0f) * 0.5f * (MMG - 1);
                    float byM = (vyM + 1.0f) * 0.5f * (MMG - 1);
                    float bsize = fmaxf((bxM - bxm + 1.0f) * (byM - bym + 1.0f), 1.0f);
                    ivbs[q][e] = __fdividef(1.0f, bsize);

                    Fax[q][e] = exp2f(KL2 * (bxm - 32.0f));
                    Fbx[q][e] = exp2f(KL2 * (31.5f - bxM));
                    Fay[q][e] = exp2f(KL2 * (bym - 32.0f));
                    Fby[q][e] = exp2f(KL2 * (31.5f - byM));
                }
            }
        }

        // ---- current pins consumed: issue next chunk's gather now; the
        //      sigmoid + smem + MMA tail below hides its latency ----
#pragma unroll
        for (int q = 0; q < 2; q++) {
            int sj = jn[q] < 0 ? 0 : jn[q];
            pvc[q] = ((const uint2*)g_pin_posH)[sj * 2 + bp];
            jc[q] = jn[q];
        }

#pragma unroll
        for (int t = 0; t < 2; t++) {
            const int gi = lane + t * 32;
#pragma unroll
            for (int q = 0; q < 2; q++) {
#pragma unroll
                for (int e = 0; e < 2; e++) {
                    float xv = 0.0f, yv = 0.0f;
                    if (act[q]) {
                        float ex0 = fminf(Fax[q][e] * Cf[t], 1e18f);
                        float ex1 = fminf(Fbx[q][e] * Df[t], 1e18f);
                        float ey0 = fminf(Fay[q][e] * Cf[t], 1e18f);
                        float ey1 = fminf(Fby[q][e] * Df[t], 1e18f);
                        float Px = (1.0f + ex0) * (1.0f + ex1);
                        float Py = (1.0f + ey0) * (1.0f + ey1);
                        float R  = __fdividef(1.0f, Px * Py);
                        xv = Py * R;
                        yv = ivbs[q][e] * Px * R;
                    }
                    XsT[e][gi][w + q * 8] = to_tf32(xv);
                    YsT[e][gi][w + q * 8] = to_tf32(yv);
                }
            }
        }
        __syncthreads();

        // rank-16 update of this warp's batch: D[i][j] += sum_k Y[k][i]*X[k][j]
#pragma unroll
        for (int ks = 0; ks < 2; ks++) {
            const int k0 = ks * 8;
            unsigned a0 = YsT[we][rm + g    ][k0 + tg    ];
            unsigned a1 = YsT[we][rm + g + 8][k0 + tg    ];
            unsigned a2 = YsT[we][rm + g    ][k0 + tg + 4];
            unsigned a3 = YsT[we][rm + g + 8][k0 + tg + 4];
#pragma unroll
            for (int nt = 0; nt < 8; nt++) {
                unsigned b0 = XsT[we][nt * 8 + g][k0 + tg    ];
                unsigned b1 = XsT[we][nt * 8 + g][k0 + tg + 4];
                mma_tf32(acc[nt][0], acc[nt][1], acc[nt][2], acc[nt][3],
                         a0, a1, a2, a3, b0, b1);
            }
        }
        __syncthreads();
    }

    // writeback: warp's batch is 2*bp + we
    {
        const int bg = 2 * bp + we;
        const int r0 = rm + g;
        const int r1 = rm + g + 8;
#pragma unroll
        for (int nt = 0; nt < 8; nt++) {
            const int col = nt * 8 + 2 * tg;
            atomicAdd(&g_rudy[bg][r0 * MMG + col    ], acc[nt][0]);
            atomicAdd(&g_rudy[bg][r0 * MMG + col + 1], acc[nt][1]);
            atomicAdd(&g_rudy[bg][r1 * MMG + col    ], acc[nt][2]);
            atomicAdd(&g_rudy[bg][r1 * MMG + col + 1], acc[nt][3]);
        }
    }

    if (lane == 0) {
        atomicAdd(&g_hpwl[2 * bp    ], hp2[0]);
        atomicAdd(&g_hpwl[2 * bp + 1], hp2[1]);
    }
}

// ---------------------------------------------------------------------------
// Phase C: 7x7 Gaussian smooth (zero-padded) + overflow penalty + finalize.
__global__ __launch_bounds__(256) void conv_kernel(float* __restrict__ out)
{
    __shared__ float tile[10][MMG];
    __shared__ float red[8];
    const int b     = blockIdx.y;
    const int slice = blockIdx.x;
    const int tid   = threadIdx.x;
    const int r0    = slice * 4;

    for (int i = tid; i < 10 * MMG; i += 256) {
        int rr = r0 - 3 + (i >> 6);
        int cc = i & 63;
        tile[i >> 6][cc] = (rr >= 0 && rr < MMG) ? g_rudy[b][rr * MMG + cc] : 0.0f;
    }
    __syncthreads();

    const float g1[7] = {0.13533528f, 0.41111229f, 0.80073740f, 1.0f,
                         0.80073740f, 0.41111229f, 0.13533528f};
    float s1 = 0.0f;
#pragma unroll
    for (int i = 0; i < 7; i++) s1 += g1[i];
    const float inv_norm = __fdividef(1.0f, s1 * s1);

    const int lr = tid >> 6;       // 0..3
    const int j  = tid & 63;
    float s = 0.0f;
#pragma unroll
    for (int di = -3; di <= 3; di++) {
        float rs = 0.0f;
#pragma unroll
        for (int dj = -3; dj <= 3; dj++) {
            int jj = j + dj;
            if (jj >= 0 && jj < MMG)
                rs = fmaf(g1[dj + 3], tile[lr + 3 + di][jj], rs);
        }
        s = fmaf(g1[di + 3], rs, s);
    }
    s *= inv_norm;
    float ov = fmaxf(s - THRESH_F, 0.0f);
    float pen = ov * ov;

#pragma unroll
    for (int o = 16; o > 0; o >>= 1)
        pen += __shfl_xor_sync(0xffffffffu, pen, o);
    if ((tid & 31) == 0) red[tid >> 5] = pen;
    __syncthreads();
    if (tid == 0) {
        float v = 0.0f;
#pragma unroll
        for (int i = 0; i < 8; i++) v += red[i];
        atomicAdd(&g_pen[b], v);
        __threadfence();
        unsigned done = atomicAdd(&g_cnt[b], 1u);
        if (done == 15u) {
            __threadfence();
            float pp = *((volatile float*)&g_pen[b]);
            float h  = *((volatile float*)&g_hpwl[b]);
            out[b] = h + W_CONG_F * pp;
        }
    }
}

// ---------------------------------------------------------------------------
extern "C" void kernel_launch(void* const* d_in, const int* in_sizes, int n_in,
                              void* d_out, int out_size)
{
    const float* positions    = nullptr;
    const int*   net_to_pin   = nullptr;
    const int*   pin_to_macro = nullptr;
    const float* pin_offsets  = nullptr;
    const float* rot_onehot   = nullptr;
    const float* net_weights  = nullptr;

    for (int i = 0; i < n_in; i++) {
        switch (in_sizes[i]) {
            case BB * VV * 2:   positions    = (const float*)d_in[i]; break;
            case NNN * MPP:     net_to_pin   = (const int*)  d_in[i]; break;
            case PP:            pin_to_macro = (const int*)  d_in[i]; break;
            case PP * 2:        pin_offsets  = (const float*)d_in[i]; break;
            case BB * VV * 4:   rot_onehot   = (const float*)d_in[i]; break;
            case NNN:           net_weights  = (const float*)d_in[i]; break;
        }
    }

    macro_prep_kernel<<<(BB * VV + 255) / 256, 256>>>(positions, rot_onehot);
    pin_pos_kernel<<<(PP + 255) / 256, 256>>>(pin_to_macro, pin_offsets);
    net_kernel<<<dim3(NET_BLOCKS, 2), 256>>>(net_to_pin, net_weights);
    conv_kernel<<<dim3(16, BB), 256>>>((float*)d_out);
}